// round 12
// baseline (speedup 1.0000x reference)
#include <cuda_runtime.h>
#include <cuda_fp16.h>
#include <math.h>
#include <stdint.h>

#define B 8
#define D 256
#define NN 1024
#define MM 1024
#define KD 64
#define VD 64
#define KVR 128

#define NSTAGE 5
// smem halves: stage = K(3072, padded) + V(2560, padded)
#define STAGE_H 5632
#define V_OFF   3072
#define STAGES_H (NSTAGE * STAGE_H)     // 28160
#define XS_OFF  STAGES_H
#define XSP 264                          // Xs [32 n][264 d]
#define QSM_OFF STAGES_H
#define KP 68                            // Qsm [32 nl][8 h][68 k]
#define SMEM_HALFS (QSM_OFF + 32 * 8 * KP)   // 45568
#define SMEM_BYTES (SMEM_HALFS * 2)           // 91136
#define OSP 520                          // epilogue Os [32 n][520 vh] @ 0

#define QSCALE 0.1803368801f   // 0.125 * log2(e)

__device__ float  g_WkvT[KVR * D];
__device__ __half g_WqP[512 * D];    // Wq A-frags fp16, pre-scaled
__device__ __half g_K[B * 32 * 2048];   // K as B-frags (k x m) per chunk
__device__ __half g_V[B * 32 * 2048];   // V as B-frags (m x v) per chunk
__device__ __half g_WoP[D * 512];    // Wo A-frags fp16

__device__ __forceinline__ float ex2(float x) {
    float r; asm("ex2.approx.f32 %0, %1;" : "=f"(r) : "f"(x)); return r;
}
__device__ __forceinline__ float rcp(float x) {
    float r; asm("rcp.approx.f32 %0, %1;" : "=f"(r) : "f"(x)); return r;
}
__device__ __forceinline__ uint32_t packh2(float a, float b) {
    __half2 h = __floats2half2_rn(a, b);
    return *reinterpret_cast<uint32_t*>(&h);
}
__device__ __forceinline__ void mmaf16(float* c, const uint32_t* a, const uint32_t* b) {
    asm volatile(
        "mma.sync.aligned.m16n8k16.row.col.f32.f16.f16.f32 "
        "{%0,%1,%2,%3}, {%4,%5,%6,%7}, {%8,%9}, {%0,%1,%2,%3};\n"
        : "+f"(c[0]), "+f"(c[1]), "+f"(c[2]), "+f"(c[3])
        : "r"(a[0]), "r"(a[1]), "r"(a[2]), "r"(a[3]), "r"(b[0]), "r"(b[1]));
}
__device__ __forceinline__ void mmaf16z(float* c, const uint32_t* a, const uint32_t* b) {
    asm volatile(
        "mma.sync.aligned.m16n8k16.row.col.f32.f16.f16.f32 "
        "{%0,%1,%2,%3}, {%4,%5,%6,%7}, {%8,%9}, {%10,%10,%10,%10};\n"
        : "=f"(c[0]), "=f"(c[1]), "=f"(c[2]), "=f"(c[3])
        : "r"(a[0]), "r"(a[1]), "r"(a[2]), "r"(a[3]), "r"(b[0]), "r"(b[1]),
          "f"(0.0f));
}
__device__ __forceinline__ void cp16(uint32_t dst, const void* src) {
    asm volatile("cp.async.cg.shared.global [%0], [%1], 16;\n"
                 :: "r"(dst), "l"(src));
}
#define CP_COMMIT() asm volatile("cp.async.commit_group;\n" ::)
#define CP_WAIT(n)  asm volatile("cp.async.wait_group %0;\n" :: "n"(n))

// ---------------- kernel 0: pack weights ----------------
__global__ void pack_weights(const float* __restrict__ Wq,
                             const float* __restrict__ Wk,
                             const float* __restrict__ Wv,
                             const float* __restrict__ Wo) {
    int i = blockIdx.x * blockDim.x + threadIdx.x;
    if (i < KVR * D) {
        int r = i / D, d = i % D;
        g_WkvT[i] = (r < 64) ? Wk[d * KD + r] : Wv[d * VD + (r - 64)];
    }
    if (i < 512 * D) {   // WqP: [w8][kc16][mi4][lane32][r4][dlt2]
        int dlt = i & 1, r = (i >> 1) & 3, ln = (i >> 3) & 31;
        int mi = (i >> 8) & 3, kc = (i >> 10) & 15, w = (i >> 14) & 7;
        int g = ln >> 2, t = ln & 3;
        int rk = w * 64 + mi * 16 + g + 8 * (r & 1);
        int d = kc * 16 + 2 * t + dlt + 8 * (r >> 1);
        int kq = rk >> 3, h = rk & 7;
        g_WqP[i] = __float2half_rn(Wq[h * (D * KD) + d * KD + kq] * QSCALE);
    }
    if (i < D * 512) {   // WoP: [w8][ks32][mi2][lane32][r4][dlt2]
        int dlt = i & 1, r = (i >> 1) & 3, ln = (i >> 3) & 31;
        int mi = (i >> 8) & 1, ks = (i >> 9) & 31, w = (i >> 14) & 7;
        int g = ln >> 2, t = ln & 3;
        int d = w * 32 + mi * 16 + g + 8 * (r & 1);
        int vh = ks * 16 + 2 * t + dlt + 8 * (r >> 1);
        g_WoP[i] = __float2half_rn(Wo[d * 512 + vh]);
    }
}

// ---------------- kernel 1: K/V projection GEMM (B-frag fp16 output) ----------------
__global__ void __launch_bounds__(256) proj_kv(const float* __restrict__ X) {
    const int b = blockIdx.z, n0 = blockIdx.x * 128;
    const float* A = g_WkvT;
    const float* Xb = X + b * (D * NN);

    __shared__ float As[16 * 136];
    __shared__ float Xs[16 * 128];

    float acc[8][8] = {};
    const int tid = threadIdx.x;
    const int tr = tid >> 4, tn = tid & 15;

    for (int dc = 0; dc < D; dc += 16) {
#pragma unroll
        for (int i = 0; i < 8; i++) {
            int idx = tid + i * 256;
            int rr = idx >> 4, c = idx & 15;
            As[c * 136 + rr] = A[rr * D + dc + c];
        }
#pragma unroll
        for (int i = 0; i < 8; i++) {
            int idx = tid + i * 256;
            int c = idx >> 7, nn = idx & 127;
            Xs[c * 128 + nn] = Xb[(dc + c) * NN + n0 + nn];
        }
        __syncthreads();
#pragma unroll
        for (int c = 0; c < 16; c++) {
            float4 a0 = *(const float4*)&As[c * 136 + tr * 4];
            float4 a1 = *(const float4*)&As[c * 136 + 64 + tr * 4];
            float4 x0 = *(const float4*)&Xs[c * 128 + tn * 4];
            float4 x1 = *(const float4*)&Xs[c * 128 + 64 + tn * 4];
            float ra[8] = {a0.x, a0.y, a0.z, a0.w, a1.x, a1.y, a1.z, a1.w};
            float rx[8] = {x0.x, x0.y, x0.z, x0.w, x1.x, x1.y, x1.z, x1.w};
#pragma unroll
            for (int i = 0; i < 8; i++)
#pragma unroll
                for (int j = 0; j < 8; j++) acc[i][j] += ra[i] * rx[j];
        }
        __syncthreads();
    }

#pragma unroll
    for (int i = 0; i < 8; i++) {
        int r = tr * 4 + (i & 3) + (i >> 2) * 64;
#pragma unroll
        for (int j = 0; j < 8; j++) {
            int n = n0 + tn * 4 + (j & 3) + (j >> 2) * 64;
            __half v = __float2half_rn(acc[i][j]);
            if (r < 64) {   // K B-frag pack: K[k][m], n-col = m
                int k = r, m = n;
                int mch = m >> 5, ml = m & 31;
                int nt = ml >> 3, gd = ml & 7;
                int ks = k >> 4, k16 = k & 15;
                int e = k16 >> 3, rem = k16 & 7, tg = rem >> 1, dlt = rem & 1;
                int ln = gd * 4 + tg;
                g_K[(b * 32 + mch) * 2048 + ks * 512 + ln * 16 + nt * 4 + e * 2 + dlt] = v;
            } else {        // V B-frag pack: V[m][v] with k-dim = m, n-col = v
                int vv = r - 64, m = n;
                int mch = m >> 5, ml = m & 31;
                int ms = ml >> 4, m16 = ml & 15;
                int e = m16 >> 3, rem = m16 & 7, tg = rem >> 1, dlt = rem & 1;
                int vt = vv >> 3, gd = vv & 7;
                int ln = gd * 4 + tg;
                g_V[(b * 32 + mch) * 2048 + ms * 1024 + ln * 32 + vt * 4 + e * 2 + dlt] = v;
            }
        }
    }
}

// phase-1: c1[mi][nt] = logits^T  (A = Q^T regs, B = K from smem)
__device__ __forceinline__ void phase1(const __half* Ks,
                                       const uint32_t Qreg[4][2][4],
                                       float c1[2][4][4], int lane) {
#pragma unroll
    for (int ks = 0; ks < 4; ks++) {
        uint4 ka = *(const uint4*)&Ks[ks * 768 + lane * 24];
        uint4 kb = *(const uint4*)&Ks[ks * 768 + lane * 24 + 8];
        uint32_t kf[4][2] = {{ka.x, ka.y}, {ka.z, ka.w}, {kb.x, kb.y}, {kb.z, kb.w}};
#pragma unroll
        for (int mi = 0; mi < 2; mi++)
#pragma unroll
            for (int nt = 0; nt < 4; nt++) {
                if (ks == 0) mmaf16z(c1[mi][nt], Qreg[0][mi], kf[nt]);
                else         mmaf16(c1[mi][nt], Qreg[ks][mi], kf[nt]);
            }
    }
}

// softmax over heads: rows r = (h&3) + 4*nl2 + 8*(h>>2); heads live in
// this lane's (c0,c2)/(c1,c3) plus lanes gid^1, gid^2 (lane xor 4, 8).
__device__ __forceinline__ void softmax_pack(float c1[2][4][4],
                                             uint32_t p01[2][4],
                                             uint32_t p23[2][4]) {
#pragma unroll
    for (int mi = 0; mi < 2; mi++)
#pragma unroll
        for (int nt = 0; nt < 4; nt++) {
            float* cc = c1[mi][nt];
            float e0 = ex2(cc[0]), e1 = ex2(cc[1]);
            float e2 = ex2(cc[2]), e3 = ex2(cc[3]);
            float s02 = e0 + e2, s13 = e1 + e3;
            s02 += __shfl_xor_sync(0xffffffffu, s02, 4);
            s02 += __shfl_xor_sync(0xffffffffu, s02, 8);
            s13 += __shfl_xor_sync(0xffffffffu, s13, 4);
            s13 += __shfl_xor_sync(0xffffffffu, s13, 8);
            float r02 = rcp(s02), r13 = rcp(s13);
            p01[mi][nt] = packh2(e0 * r02, e1 * r13);
            p23[mi][nt] = packh2(e2 * r02, e3 * r13);
        }
}

// phase-3: Oacc[mi][vt] += attn^T (A from packs) x V (B from smem)
__device__ __forceinline__ void phase3(const __half* Vs,
                                       const uint32_t p01[2][4],
                                       const uint32_t p23[2][4],
                                       float Oacc[2][8][4], int lane) {
#pragma unroll
    for (int ms = 0; ms < 2; ms++) {
        uint4 va = *(const uint4*)&Vs[ms * 1280 + lane * 40];
        uint4 vb = *(const uint4*)&Vs[ms * 1280 + lane * 40 + 8];
        uint4 vc = *(const uint4*)&Vs[ms * 1280 + lane * 40 + 16];
        uint4 vd = *(const uint4*)&Vs[ms * 1280 + lane * 40 + 24];
        uint32_t vf[8][2] = {{va.x, va.y}, {va.z, va.w}, {vb.x, vb.y}, {vb.z, vb.w},
                             {vc.x, vc.y}, {vc.z, vc.w}, {vd.x, vd.y}, {vd.z, vd.w}};
#pragma unroll
        for (int mi = 0; mi < 2; mi++) {
            uint32_t af[4] = {p01[mi][2 * ms], p23[mi][2 * ms],
                              p01[mi][2 * ms + 1], p23[mi][2 * ms + 1]};
#pragma unroll
            for (int vt = 0; vt < 8; vt++)
                mmaf16(Oacc[mi][vt], af, vf[vt]);
        }
    }
}

// ---------------- kernel 2: fused main ----------------
__global__ void __launch_bounds__(256, 1) mqa_main(const float* __restrict__ x,
                                                   float* __restrict__ out) {
    extern __shared__ __half smh[];

    const int b = blockIdx.y;
    const int n0 = blockIdx.x * 32;
    const int tid = threadIdx.x;
    const int lane = tid & 31;
    const int wgrp = tid >> 5;   // 0..7
    const int gid = lane >> 2;
    const int tig = lane & 3;

    const __half* Kg = g_K + b * 65536;
    const __half* Vg = g_V + b * 65536;

    // per-thread cp.async dst offsets (halves, padded layouts)
    const int dK = (tid >> 6) * 768 + ((tid & 63) >> 1) * 24 + (tid & 1) * 8;
    const int dV = V_OFF + (tid >> 7) * 1280 + ((tid >> 2) & 31) * 40 + (tid & 3) * 8;

    const uint32_t smem_u32 = (uint32_t)__cvta_generic_to_shared(smh);
#pragma unroll
    for (int s = 0; s < 4; s++) {
        cp16(smem_u32 + (s * STAGE_H + dK) * 2, Kg + s * 2048 + tid * 8);
        cp16(smem_u32 + (s * STAGE_H + dV) * 2, Vg + s * 2048 + tid * 8);
        CP_COMMIT();
    }

    // ---- prologue: Q projection (fp16 mma), then Q^T A-frags ----
    uint32_t Qreg[4][2][4];
    {
        __half* Xs = smh + XS_OFF;   // [32 n][264 d]
        const float* Xb = x + b * (D * NN);
#pragma unroll
        for (int i = 0; i < 32; i++) {
            int idx = tid + i * 256;
            int dd = idx >> 5, nn2 = idx & 31;
            Xs[nn2 * XSP + dd] = __float2half_rn(Xb[dd * NN + n0 + nn2]);
        }
        __syncthreads();

        float qa[4][4][4] = {};
        const __half* WqPw = g_WqP + wgrp * 16384;
#pragma unroll 4
        for (int kc = 0; kc < 16; kc++) {
            uint32_t bf[4][2];
#pragma unroll
            for (int ni = 0; ni < 4; ni++) {
                bf[ni][0] = *(const uint32_t*)&Xs[(ni * 8 + gid) * XSP + kc * 16 + 2 * tig];
                bf[ni][1] = *(const uint32_t*)&Xs[(ni * 8 + gid) * XSP + kc * 16 + 2 * tig + 8];
            }
#pragma unroll
            for (int mi = 0; mi < 4; mi++) {
                uint4 a = *(const uint4*)&WqPw[(kc * 4 + mi) * 256 + lane * 8];
#pragma unroll
                for (int ni = 0; ni < 4; ni++)
                    mmaf16(qa[mi][ni], (const uint32_t*)&a, bf[ni]);
            }
        }
        __syncthreads();   // Xs reads done

        __half* Qsm = smh + QSM_OFF;   // [nl32][h8][KP]
#pragma unroll
        for (int mi = 0; mi < 4; mi++)
#pragma unroll
            for (int ni = 0; ni < 4; ni++)
#pragma unroll
                for (int r = 0; r < 4; r++) {
                    int rk = wgrp * 64 + mi * 16 + gid + 8 * (r >> 1);
                    int nl = ni * 8 + 2 * tig + (r & 1);
                    Qsm[(nl * 8 + (rk & 7)) * KP + (rk >> 3)] =
                        __float2half_rn(qa[mi][ni][r]);
                }
        __syncthreads();

        // A-frags: row gid -> (nl2=(gid>>2), h=gid&3); row gid+8 -> h+4
#pragma unroll
        for (int ks = 0; ks < 4; ks++)
#pragma unroll
            for (int mi = 0; mi < 2; mi++) {
                int nlb = wgrp * 4 + 2 * mi + (gid >> 2);
                int r01 = (nlb * 8 + (gid & 3)) * KP;
                int r23 = (nlb * 8 + (gid & 3) + 4) * KP;
                int kk = ks * 16 + 2 * tig;
                Qreg[ks][mi][0] = *(const uint32_t*)&Qsm[r01 + kk];
                Qreg[ks][mi][1] = *(const uint32_t*)&Qsm[r23 + kk];
                Qreg[ks][mi][2] = *(const uint32_t*)&Qsm[r01 + kk + 8];
                Qreg[ks][mi][3] = *(const uint32_t*)&Qsm[r23 + kk + 8];
            }
    }

    // ---- stage 0 ready; phase1(0) ----
    CP_WAIT(3);
    __syncthreads();

    float c1[2][4][4];
    phase1(smh, Qreg, c1, lane);

    float Oacc[2][8][4] = {};
    int sW = 4, sP1 = 1, sP3 = 0;

#pragma unroll 1
    for (int mch = 0; mch < 31; mch++) {
        CP_WAIT(2);
        __syncthreads();

        if (mch + 4 < 32) {
            cp16(smem_u32 + (sW * STAGE_H + dK) * 2, Kg + (mch + 4) * 2048 + tid * 8);
            cp16(smem_u32 + (sW * STAGE_H + dV) * 2, Vg + (mch + 4) * 2048 + tid * 8);
        }
        CP_COMMIT();

        uint32_t p01[2][4], p23[2][4];
        softmax_pack(c1, p01, p23);

        // phase1 of next chunk fills the softmax stall holes (c1 consumed)
        phase1(smh + sP1 * STAGE_H, Qreg, c1, lane);

        phase3(smh + sP3 * STAGE_H + V_OFF, p01, p23, Oacc, lane);

        sW = (sW == NSTAGE - 1) ? 0 : sW + 1;
        sP1 = (sP1 == NSTAGE - 1) ? 0 : sP1 + 1;
        sP3 = (sP3 == NSTAGE - 1) ? 0 : sP3 + 1;
    }

    // peeled final chunk
    {
        uint32_t p01[2][4], p23[2][4];
        softmax_pack(c1, p01, p23);
        phase3(smh + sP3 * STAGE_H + V_OFF, p01, p23, Oacc, lane);
    }
    CP_WAIT(0);
    __syncthreads();

    // ---- epilogue: stage O^T C-frags into Os[n][vh] ----
    __half* Os = smh;   // [32][OSP]
#pragma unroll
    for (int mi = 0; mi < 2; mi++) {
        int nl = wgrp * 4 + 2 * mi + (gid >> 2);
        int hb = gid & 3;
#pragma unroll
        for (int vt = 0; vt < 8; vt++) {
            int v0 = vt * 8 + 2 * tig;
            Os[nl * OSP + v0 * 8 + hb]           = __float2half_rn(Oacc[mi][vt][0]);
            Os[nl * OSP + (v0 + 1) * 8 + hb]     = __float2half_rn(Oacc[mi][vt][1]);
            Os[nl * OSP + v0 * 8 + hb + 4]       = __float2half_rn(Oacc[mi][vt][2]);
            Os[nl * OSP + (v0 + 1) * 8 + hb + 4] = __float2half_rn(Oacc[mi][vt][3]);
        }
    }
    __syncthreads();

    // ---- res = Wo @ O (fp16 mma, Wo A-frags from gmem/L2) ----
    float racc[2][4][4] = {};
    const __half* WoP = g_WoP + wgrp * 16384;
#pragma unroll 2
    for (int ks = 0; ks < 32; ks++) {
        uint4 a0 = *(const uint4*)&WoP[(ks * 2 + 0) * 256 + lane * 8];
        uint4 a1 = *(const uint4*)&WoP[(ks * 2 + 1) * 256 + lane * 8];
#pragma unroll
        for (int ni = 0; ni < 4; ni++) {
            uint32_t bf[2];
            bf[0] = *(const uint32_t*)&Os[(ni * 8 + gid) * OSP + ks * 16 + 2 * tig];
            bf[1] = *(const uint32_t*)&Os[(ni * 8 + gid) * OSP + ks * 16 + 2 * tig + 8];
            mmaf16(racc[0][ni], (const uint32_t*)&a0, bf);
            mmaf16(racc[1][ni], (const uint32_t*)&a1, bf);
        }
    }

    float* ob = out + b * (D * NN);
#pragma unroll
    for (int mi = 0; mi < 2; mi++)
#pragma unroll
        for (int ni = 0; ni < 4; ni++) {
            int d = wgrp * 32 + mi * 16 + gid;
            *(float2*)&ob[d * NN + n0 + ni * 8 + tig * 2] =
                make_float2(racc[mi][ni][0], racc[mi][ni][1]);
            *(float2*)&ob[(d + 8) * NN + n0 + ni * 8 + tig * 2] =
                make_float2(racc[mi][ni][2], racc[mi][ni][3]);
        }
}

// ---------------- launcher ----------------
extern "C" void kernel_launch(void* const* d_in, const int* in_sizes, int n_in,
                              void* d_out, int out_size) {
    const float* x     = (const float*)d_in[0];
    const float* value = (const float*)d_in[1];
    const float* Wq    = (const float*)d_in[2];
    const float* Wk    = (const float*)d_in[3];
    const float* Wv    = (const float*)d_in[4];
    const float* Wo    = (const float*)d_in[5];
    float* out = (float*)d_out;

    pack_weights<<<512, 256>>>(Wq, Wk, Wv, Wo);
    proj_kv<<<dim3(MM / 128, 1, B), 256>>>(value);

    cudaFuncSetAttribute(mqa_main, cudaFuncAttributeMaxDynamicSharedMemorySize, SMEM_BYTES);
    mqa_main<<<dim3(NN / 32, B), 256, SMEM_BYTES>>>(x, out);
}